// round 11
// baseline (speedup 1.0000x reference)
#include <cuda_runtime.h>

// Problem constants
#define Bb 4
#define Ss 2048
#define Dd 1024
#define Hh 16
#define DHd 64
#define TOK (Bb*Ss)          // 8192
#define NHD (Hh*DHd)         // 1024

// Scratch (device globals — no allocation allowed in kernel_launch)
__device__ float g_Q[TOK*NHD];
__device__ float g_K[TOK*NHD];
__device__ float g_V[TOK*NHD];
__device__ float g_X[TOK*NHD];

// ---------------------------------------------------------------------------
// SGEMM: C[M,N] = alpha * (A[M,K] @ B[K,N] + bias[N])   (all row-major fp32)
// 128x128 block tile, BK=16, 256 threads, 8x8 per-thread microtile.
// ---------------------------------------------------------------------------
__global__ __launch_bounds__(256, 2)
void sgemm_bias_kernel(const float* __restrict__ A, const float* __restrict__ Bm,
                       const float* __restrict__ bias, float* __restrict__ C,
                       int M, int N, int K, float alpha)
{
    constexpr int BM = 128, BN = 128, BK = 16;
    __shared__ float As[BK][BM + 4];   // transposed A tile (k-major), padded
    __shared__ float Bs[BK][BN];

    const int tid = threadIdx.x;            // 0..255
    const int bm  = blockIdx.y * BM;
    const int bn  = blockIdx.x * BN;
    const int tx  = tid & 15;
    const int ty  = tid >> 4;

    // global->smem load mapping
    const int arow = tid >> 2;               // 0..63
    const int acol = (tid & 3) * 4;          // 0,4,8,12
    const int brow = tid >> 5;               // 0..7
    const int bcol = (tid & 31) * 4;         // 0..124

    float acc[8][8];
#pragma unroll
    for (int i = 0; i < 8; i++)
#pragma unroll
        for (int j = 0; j < 8; j++) acc[i][j] = 0.f;

    for (int k0 = 0; k0 < K; k0 += BK) {
#pragma unroll
        for (int p = 0; p < 2; p++) {
            float4 a = *reinterpret_cast<const float4*>(
                &A[(long)(bm + arow + p * 64) * K + k0 + acol]);
            As[acol + 0][arow + p * 64] = a.x;
            As[acol + 1][arow + p * 64] = a.y;
            As[acol + 2][arow + p * 64] = a.z;
            As[acol + 3][arow + p * 64] = a.w;
        }
#pragma unroll
        for (int p = 0; p < 2; p++) {
            *reinterpret_cast<float4*>(&Bs[brow + p * 8][bcol]) =
                *reinterpret_cast<const float4*>(
                    &Bm[(long)(k0 + brow + p * 8) * N + bn + bcol]);
        }
        __syncthreads();

#pragma unroll
        for (int kk = 0; kk < BK; kk++) {
            float a[8], b[8];
            *reinterpret_cast<float4*>(&a[0]) =
                *reinterpret_cast<const float4*>(&As[kk][ty * 8]);
            *reinterpret_cast<float4*>(&a[4]) =
                *reinterpret_cast<const float4*>(&As[kk][ty * 8 + 4]);
            *reinterpret_cast<float4*>(&b[0]) =
                *reinterpret_cast<const float4*>(&Bs[kk][tx * 8]);
            *reinterpret_cast<float4*>(&b[4]) =
                *reinterpret_cast<const float4*>(&Bs[kk][tx * 8 + 4]);
#pragma unroll
            for (int i = 0; i < 8; i++)
#pragma unroll
                for (int j = 0; j < 8; j++)
                    acc[i][j] = fmaf(a[i], b[j], acc[i][j]);
        }
        __syncthreads();
    }

#pragma unroll
    for (int i = 0; i < 8; i++) {
        int row = bm + ty * 8 + i;
#pragma unroll
        for (int j = 0; j < 8; j += 4) {
            int col = bn + tx * 8 + j;
            float4 o;
            o.x = alpha * (acc[i][j + 0] + bias[col + 0]);
            o.y = alpha * (acc[i][j + 1] + bias[col + 1]);
            o.z = alpha * (acc[i][j + 2] + bias[col + 2]);
            o.w = alpha * (acc[i][j + 3] + bias[col + 3]);
            *reinterpret_cast<float4*>(&C[(long)row * N + col]) = o;
        }
    }
}

// ---------------------------------------------------------------------------
// Flash attention (fp32): per (b,h), BQ=128 queries per CTA, loop 64-key blocks.
// Q is pre-scaled by 1/sqrt(DH) in the projection. Online softmax.
// Thread layout: 256 thr, tx=tid&15 (4 cols each), ty=tid>>4 (8 rows each).
// ---------------------------------------------------------------------------
__global__ __launch_bounds__(256, 2)
void flash_attn_kernel(const float* __restrict__ Q, const float* __restrict__ K,
                       const float* __restrict__ V, float* __restrict__ X)
{
    extern __shared__ float sm[];
    float* Qs = sm;                  // [64][128]  d-major (transposed)
    float* Ks = Qs + 64 * 128;       // [64][64]   d-major (transposed)
    float* Vs = Ks + 64 * 64;        // [64][64]   kk-major
    float* Ps = Vs + 64 * 64;        // [128][64]  row-major probabilities

    const int tid = threadIdx.x;
    const int tx = tid & 15;
    const int ty = tid >> 4;
    const int bh = blockIdx.y;        // 0..63
    const int b  = bh >> 4;           // / H
    const int h  = bh & 15;           // % H
    const int q0 = blockIdx.x * 128;

    const long base = (long)b * Ss * NHD + (long)h * DHd; // token0 of this head
    const float* Qb = Q + base + (long)q0 * NHD;
    const float* Kb = K + base;
    const float* Vb = V + base;

    // Load Q tile transposed: Qs[d][r]
    for (int idx = tid; idx < 128 * 64 / 4; idx += 256) {
        int r  = idx >> 4;
        int d4 = (idx & 15) * 4;
        float4 v = *reinterpret_cast<const float4*>(&Qb[(long)r * NHD + d4]);
        Qs[(d4 + 0) * 128 + r] = v.x;
        Qs[(d4 + 1) * 128 + r] = v.y;
        Qs[(d4 + 2) * 128 + r] = v.z;
        Qs[(d4 + 3) * 128 + r] = v.w;
    }

    float o[8][4];
    float m[8], l[8];
#pragma unroll
    for (int i = 0; i < 8; i++) {
        m[i] = -1e30f; l[i] = 0.f;
#pragma unroll
        for (int j = 0; j < 4; j++) o[i][j] = 0.f;
    }

    for (int kb = 0; kb < Ss; kb += 64) {
        __syncthreads();   // protect Ks/Vs/Ps reuse (also covers initial Q load)

        // Load K transposed + V direct
        for (int idx = tid; idx < 64 * 64 / 4; idx += 256) {
            int c  = idx >> 4;
            int d4 = (idx & 15) * 4;
            float4 kv = *reinterpret_cast<const float4*>(
                &Kb[(long)(kb + c) * NHD + d4]);
            Ks[(d4 + 0) * 64 + c] = kv.x;
            Ks[(d4 + 1) * 64 + c] = kv.y;
            Ks[(d4 + 2) * 64 + c] = kv.z;
            Ks[(d4 + 3) * 64 + c] = kv.w;
            float4 vv = *reinterpret_cast<const float4*>(
                &Vb[(long)(kb + c) * NHD + d4]);
            *reinterpret_cast<float4*>(&Vs[c * 64 + d4]) = vv;
        }
        __syncthreads();

        // S = Q K^T  (rows ty*8+i, key-cols tx*4+j)
        float s[8][4];
#pragma unroll
        for (int i = 0; i < 8; i++)
#pragma unroll
            for (int j = 0; j < 4; j++) s[i][j] = 0.f;

#pragma unroll 8
        for (int d = 0; d < 64; d++) {
            float a[8], kx[4];
            *reinterpret_cast<float4*>(&a[0]) =
                *reinterpret_cast<const float4*>(&Qs[d * 128 + ty * 8]);
            *reinterpret_cast<float4*>(&a[4]) =
                *reinterpret_cast<const float4*>(&Qs[d * 128 + ty * 8 + 4]);
            *reinterpret_cast<float4*>(&kx[0]) =
                *reinterpret_cast<const float4*>(&Ks[d * 64 + tx * 4]);
#pragma unroll
            for (int i = 0; i < 8; i++)
#pragma unroll
                for (int j = 0; j < 4; j++)
                    s[i][j] = fmaf(a[i], kx[j], s[i][j]);
        }

        // Online softmax (row reductions across the 16 tx lanes)
#pragma unroll
        for (int i = 0; i < 8; i++) {
            float mb = fmaxf(fmaxf(s[i][0], s[i][1]), fmaxf(s[i][2], s[i][3]));
#pragma unroll
            for (int off = 8; off; off >>= 1)
                mb = fmaxf(mb, __shfl_xor_sync(0xffffffffu, mb, off));
            float mn = fmaxf(m[i], mb);
            float al = __expf(m[i] - mn);
            m[i] = mn;
            float p[4];
            float ps = 0.f;
#pragma unroll
            for (int j = 0; j < 4; j++) { p[j] = __expf(s[i][j] - mn); ps += p[j]; }
            *reinterpret_cast<float4*>(&Ps[(ty * 8 + i) * 64 + tx * 4]) =
                *reinterpret_cast<float4*>(p);
#pragma unroll
            for (int off = 8; off; off >>= 1)
                ps += __shfl_xor_sync(0xffffffffu, ps, off);
            l[i] = l[i] * al + ps;
#pragma unroll
            for (int j = 0; j < 4; j++) o[i][j] *= al;
        }
        __syncthreads();

        // O += P @ V  (dh cols tx*4+j)
#pragma unroll 8
        for (int kk = 0; kk < 64; kk++) {
            float vj[4];
            *reinterpret_cast<float4*>(&vj[0]) =
                *reinterpret_cast<const float4*>(&Vs[kk * 64 + tx * 4]);
#pragma unroll
            for (int i = 0; i < 8; i++) {
                float p = Ps[(ty * 8 + i) * 64 + kk];   // broadcast within half-warp
#pragma unroll
                for (int j = 0; j < 4; j++)
                    o[i][j] = fmaf(p, vj[j], o[i][j]);
            }
        }
    }

    // Normalize and write X[b, q, h, :]
    float* Xb = X + base + (long)q0 * NHD;
#pragma unroll
    for (int i = 0; i < 8; i++) {
        float inv = 1.f / l[i];
        float4 w;
        w.x = o[i][0] * inv; w.y = o[i][1] * inv;
        w.z = o[i][2] * inv; w.w = o[i][3] * inv;
        *reinterpret_cast<float4*>(&Xb[(long)(ty * 8 + i) * NHD + tx * 4]) = w;
    }
}

// ---------------------------------------------------------------------------
extern "C" void kernel_launch(void* const* d_in, const int* in_sizes, int n_in,
                              void* d_out, int out_size)
{
    const float* xq = (const float*)d_in[0];
    const float* xkv = (const float*)d_in[1];
    const float* Wq = (const float*)d_in[2];
    const float* bq = (const float*)d_in[3];
    const float* Wk = (const float*)d_in[4];
    const float* bk = (const float*)d_in[5];
    const float* Wv = (const float*)d_in[6];
    const float* bv = (const float*)d_in[7];
    const float* Wo = (const float*)d_in[8];
    const float* bo = (const float*)d_in[9];
    float* out = (float*)d_out;

    float *qp, *kp, *vp, *xp;
    cudaGetSymbolAddress((void**)&qp, g_Q);
    cudaGetSymbolAddress((void**)&kp, g_K);
    cudaGetSymbolAddress((void**)&vp, g_V);
    cudaGetSymbolAddress((void**)&xp, g_X);

    dim3 gg(NHD / 128, TOK / 128);   // (8, 64)

    // QKV projections; fold 1/sqrt(DH) into Q (scale applies after bias in ref)
    sgemm_bias_kernel<<<gg, 256>>>(xq,  Wq, bq, qp, TOK, NHD, Dd, 0.125f);
    sgemm_bias_kernel<<<gg, 256>>>(xkv, Wk, bk, kp, TOK, NHD, Dd, 1.0f);
    sgemm_bias_kernel<<<gg, 256>>>(xkv, Wv, bv, vp, TOK, NHD, Dd, 1.0f);

    // Attention
    cudaFuncSetAttribute(flash_attn_kernel,
                         cudaFuncAttributeMaxDynamicSharedMemorySize, 98304);
    dim3 ga(Ss / 128, Bb * Hh);      // (16, 64)
    flash_attn_kernel<<<ga, 256, 98304>>>(qp, kp, vp, xp);

    // Output projection
    sgemm_bias_kernel<<<gg, 256>>>(xp, Wo, bo, out, TOK, Dd, NHD, 1.0f);
}

// round 15
// speedup vs baseline: 1.3357x; 1.3357x over previous
#include <cuda_runtime.h>
#include <cuda_bf16.h>
#include <cstdint>

// Problem constants
#define Bb 4
#define Ss 2048
#define Dd 1024
#define Hh 16
#define DHd 64
#define TOK (Bb*Ss)          // 8192
#define NHD (Hh*DHd)         // 1024
#define KP  3072             // split-K' = 3*1024

// ---------------- scratch (device globals; no allocs allowed) ----------------
__device__ float g_Q[TOK*NHD];
__device__ float g_K[TOK*NHD];
__device__ float g_V[TOK*NHD];
__device__ float g_X[TOK*NHD];
__device__ __nv_bfloat16 g_Aq [(size_t)TOK*KP];
__device__ __nv_bfloat16 g_Akv[(size_t)TOK*KP];
__device__ __nv_bfloat16 g_Ax [(size_t)TOK*KP];
__device__ __nv_bfloat16 g_Bq [(size_t)NHD*KP];
__device__ __nv_bfloat16 g_Bk [(size_t)NHD*KP];
__device__ __nv_bfloat16 g_Bv [(size_t)NHD*KP];
__device__ __nv_bfloat16 g_Bo [(size_t)Dd*KP];

// ---------------- helpers ----------------
__device__ __forceinline__ uint32_t smem_u32(const void* p) {
    uint32_t a;
    asm("{ .reg .u64 t; cvta.to.shared.u64 t, %1; cvt.u32.u64 %0, t; }" : "=r"(a) : "l"(p));
    return a;
}
__device__ __forceinline__ void cp_async16(uint32_t dst, const void* src) {
    asm volatile("cp.async.cg.shared.global [%0], [%1], 16;" :: "r"(dst), "l"(src) : "memory");
}
__device__ __forceinline__ void ldsm_x4(uint32_t* r, uint32_t addr) {
    asm volatile("ldmatrix.sync.aligned.m8n8.x4.shared.b16 {%0,%1,%2,%3}, [%4];"
                 : "=r"(r[0]), "=r"(r[1]), "=r"(r[2]), "=r"(r[3]) : "r"(addr));
}
__device__ __forceinline__ void mma16816(float* d, const uint32_t* a, uint32_t b0, uint32_t b1) {
    asm volatile(
        "mma.sync.aligned.m16n8k16.row.col.f32.bf16.bf16.f32 "
        "{%0,%1,%2,%3}, {%4,%5,%6,%7}, {%8,%9}, {%0,%1,%2,%3};"
        : "+f"(d[0]), "+f"(d[1]), "+f"(d[2]), "+f"(d[3])
        : "r"(a[0]), "r"(a[1]), "r"(a[2]), "r"(a[3]), "r"(b0), "r"(b1));
}

// ---------------------------------------------------------------------------
// split conversions:  fp32 X[M,K] -> bf16 A'[M,3K] = [hi | hi | lo]
// ---------------------------------------------------------------------------
__global__ void split_act_kernel(const float* __restrict__ X,
                                 __nv_bfloat16* __restrict__ P, int M, int K)
{
    long i = (long)blockIdx.x * blockDim.x + threadIdx.x;  // group of 4 elems
    long total = (long)M * K / 4;
    if (i >= total) return;
    int m  = (int)(i / (K / 4));
    int k4 = (int)(i % (K / 4)) * 4;
    float4 v = *reinterpret_cast<const float4*>(&X[(long)m * K + k4]);
    __nv_bfloat16 h0 = __float2bfloat16(v.x), h1 = __float2bfloat16(v.y);
    __nv_bfloat16 h2 = __float2bfloat16(v.z), h3 = __float2bfloat16(v.w);
    __nv_bfloat16 l0 = __float2bfloat16(v.x - __bfloat162float(h0));
    __nv_bfloat16 l1 = __float2bfloat16(v.y - __bfloat162float(h1));
    __nv_bfloat16 l2 = __float2bfloat16(v.z - __bfloat162float(h2));
    __nv_bfloat16 l3 = __float2bfloat16(v.w - __bfloat162float(h3));
    uint2 hh, ll;
    hh.x = ((uint32_t)__bfloat16_as_ushort(h1) << 16) | __bfloat16_as_ushort(h0);
    hh.y = ((uint32_t)__bfloat16_as_ushort(h3) << 16) | __bfloat16_as_ushort(h2);
    ll.x = ((uint32_t)__bfloat16_as_ushort(l1) << 16) | __bfloat16_as_ushort(l0);
    ll.y = ((uint32_t)__bfloat16_as_ushort(l3) << 16) | __bfloat16_as_ushort(l2);
    long base = (long)m * (3 * K) + k4;
    *reinterpret_cast<uint2*>(&P[base])         = hh;   // seg0: hi
    *reinterpret_cast<uint2*>(&P[base + K])     = hh;   // seg1: hi
    *reinterpret_cast<uint2*>(&P[base + 2 * K]) = ll;   // seg2: lo
}

// fp32 W[K,N] -> bf16 B'[N,3K] = rows n: [Wh(:,n) | Wl(:,n) | Wh(:,n)]
__global__ void split_wt_kernel(const float* __restrict__ W,
                                __nv_bfloat16* __restrict__ P, int K, int N)
{
    __shared__ float sm[32][33];
    int n0 = blockIdx.x * 32, k0 = blockIdx.y * 32;
    int tx = threadIdx.x, ty = threadIdx.y;
    sm[ty][tx] = W[(long)(k0 + ty) * N + n0 + tx];
    __syncthreads();
    float v = sm[tx][ty];                 // = W[k0+tx][n0+ty]
    int n = n0 + ty, k = k0 + tx;
    __nv_bfloat16 h = __float2bfloat16(v);
    __nv_bfloat16 l = __float2bfloat16(v - __bfloat162float(h));
    long base = (long)n * (3 * K);
    P[base + k]         = h;              // seg0: hi  (pairs with A hi)
    P[base + K + k]     = l;              // seg1: lo  (pairs with A hi)
    P[base + 2 * K + k] = h;              // seg2: hi  (pairs with A lo)
}

// ---------------------------------------------------------------------------
// HMMA (mma.sync bf16) GEMM: C[M,N] = alpha*(A'[M,3K] @ B'[N,3K]^T + bias[N])
// CTA tile 128x128, BK=32, 3-stage cp.async pipeline, 8 warps (4m x 2n),
// warp tile 32x64, mma.m16n8k16, fp32 accumulate.
// Smem rows padded to 40 halfs (80B) -> conflict-free ldmatrix.
// ---------------------------------------------------------------------------
#define GSTRIDE 40                       // halfs per smem row
#define STAGE_BYTES (2 * 128 * GSTRIDE * 2)   // A+B per stage = 20480
#define NSTAGE 3

__global__ __launch_bounds__(256, 2)
void gemm_mma_kernel(const __nv_bfloat16* __restrict__ A,
                     const __nv_bfloat16* __restrict__ Bp,
                     const float* __restrict__ bias, float* __restrict__ C,
                     int N, float alpha)
{
    constexpr int NIT = KP / 32;         // 96
    extern __shared__ char smem[];
    const uint32_t smb = smem_u32(smem);

    const int tid  = threadIdx.x;
    const int lane = tid & 31, w = tid >> 5;
    const int wm = (w & 3) * 32;         // warp m offset in tile
    const int wn = (w >> 2) * 64;        // warp n offset in tile
    const int bm = blockIdx.y * 128, bn = blockIdx.x * 128;

    const __nv_bfloat16* Abase = A  + (size_t)bm * KP;
    const __nv_bfloat16* Bbase = Bp + (size_t)bn * KP;

    auto load_stage = [&](int st) {
        uint32_t base = smb + (uint32_t)(st % NSTAGE) * STAGE_BYTES;
        int k0 = st * 32;
#pragma unroll
        for (int j = 0; j < 2; j++) {     // A: 512 16B chunks
            int c = tid + 256 * j;
            int row = c >> 2, cc = (c & 3);
            cp_async16(base + row * (GSTRIDE * 2) + cc * 16,
                       Abase + (size_t)row * KP + k0 + cc * 8);
        }
#pragma unroll
        for (int j = 0; j < 2; j++) {     // B: 512 16B chunks
            int c = tid + 256 * j;
            int row = c >> 2, cc = (c & 3);
            cp_async16(base + 128 * (GSTRIDE * 2) + row * (GSTRIDE * 2) + cc * 16,
                       Bbase + (size_t)row * KP + k0 + cc * 8);
        }
    };

    float acc[2][8][4];
#pragma unroll
    for (int mi = 0; mi < 2; mi++)
#pragma unroll
        for (int ni = 0; ni < 8; ni++)
#pragma unroll
            for (int j = 0; j < 4; j++) acc[mi][ni][j] = 0.f;

    // prologue
    load_stage(0); asm volatile("cp.async.commit_group;" ::: "memory");
    load_stage(1); asm volatile("cp.async.commit_group;" ::: "memory");

    // precomputed per-lane ldmatrix sub-offsets
    const uint32_t a_row = (lane & 15);
    const uint32_t a_kof = ((lane >> 4) & 1) * 8;
    const uint32_t b_row = ((lane >> 4) & 1) * 8 + (lane & 7);
    const uint32_t b_kof = ((lane >> 3) & 1) * 8;

    for (int kt = 0; kt < NIT; kt++) {
        asm volatile("cp.async.wait_group %0;" :: "n"(NSTAGE - 2) : "memory");
        __syncthreads();

        if (kt + NSTAGE - 1 < NIT) load_stage(kt + NSTAGE - 1);
        asm volatile("cp.async.commit_group;" ::: "memory");

        uint32_t sa = smb + (uint32_t)(kt % NSTAGE) * STAGE_BYTES;
        uint32_t sb = sa + 128 * (GSTRIDE * 2);
#pragma unroll
        for (int kh = 0; kh < 2; kh++) {
            int k16 = kh * 16;
            uint32_t a[2][4], b[4][4];
#pragma unroll
            for (int mi = 0; mi < 2; mi++)
                ldsm_x4(a[mi], sa + (wm + mi * 16 + a_row) * (GSTRIDE * 2)
                               + (k16 + a_kof) * 2);
#pragma unroll
            for (int nq = 0; nq < 4; nq++)
                ldsm_x4(b[nq], sb + (wn + nq * 16 + b_row) * (GSTRIDE * 2)
                               + (k16 + b_kof) * 2);
#pragma unroll
            for (int mi = 0; mi < 2; mi++)
#pragma unroll
                for (int ni = 0; ni < 8; ni++)
                    mma16816(acc[mi][ni], a[mi],
                             b[ni >> 1][(ni & 1) * 2],
                             b[ni >> 1][(ni & 1) * 2 + 1]);
        }
        __syncthreads();
    }

    // epilogue: alpha*(acc + bias)
    const int r0 = lane >> 2;
    const int c0 = (lane & 3) * 2;
#pragma unroll
    for (int mi = 0; mi < 2; mi++) {
        int grow = bm + wm + mi * 16 + r0;
#pragma unroll
        for (int ni = 0; ni < 8; ni++) {
            int gcol = bn + wn + ni * 8 + c0;
            float b0 = __ldg(bias + gcol), b1 = __ldg(bias + gcol + 1);
            float2 o0, o1;
            o0.x = alpha * (acc[mi][ni][0] + b0);
            o0.y = alpha * (acc[mi][ni][1] + b1);
            o1.x = alpha * (acc[mi][ni][2] + b0);
            o1.y = alpha * (acc[mi][ni][3] + b1);
            *reinterpret_cast<float2*>(&C[(size_t)grow * N + gcol]) = o0;
            *reinterpret_cast<float2*>(&C[(size_t)(grow + 8) * N + gcol]) = o1;
        }
    }
}

// ---------------------------------------------------------------------------
// Flash attention (fp32) — unchanged.
// ---------------------------------------------------------------------------
__global__ __launch_bounds__(256, 2)
void flash_attn_kernel(const float* __restrict__ Q, const float* __restrict__ K,
                       const float* __restrict__ V, float* __restrict__ X)
{
    extern __shared__ float sm[];
    float* Qs = sm;                  // [64][128]  d-major
    float* Ks = Qs + 64 * 128;       // [64][64]   d-major
    float* Vs = Ks + 64 * 64;        // [64][64]   kk-major
    float* Ps = Vs + 64 * 64;        // [128][64]

    const int tid = threadIdx.x;
    const int tx = tid & 15;
    const int ty = tid >> 4;
    const int bh = blockIdx.y;
    const int b  = bh >> 4;
    const int h  = bh & 15;
    const int q0 = blockIdx.x * 128;

    const long base = (long)b * Ss * NHD + (long)h * DHd;
    const float* Qb = Q + base + (long)q0 * NHD;
    const float* Kb = K + base;
    const float* Vb = V + base;

    for (int idx = tid; idx < 128 * 64 / 4; idx += 256) {
        int r  = idx >> 4;
        int d4 = (idx & 15) * 4;
        float4 v = *reinterpret_cast<const float4*>(&Qb[(long)r * NHD + d4]);
        Qs[(d4 + 0) * 128 + r] = v.x;
        Qs[(d4 + 1) * 128 + r] = v.y;
        Qs[(d4 + 2) * 128 + r] = v.z;
        Qs[(d4 + 3) * 128 + r] = v.w;
    }

    float o[8][4];
    float m[8], l[8];
#pragma unroll
    for (int i = 0; i < 8; i++) {
        m[i] = -1e30f; l[i] = 0.f;
#pragma unroll
        for (int j = 0; j < 4; j++) o[i][j] = 0.f;
    }

    for (int kb = 0; kb < Ss; kb += 64) {
        __syncthreads();
        for (int idx = tid; idx < 64 * 64 / 4; idx += 256) {
            int c  = idx >> 4;
            int d4 = (idx & 15) * 4;
            float4 kv = *reinterpret_cast<const float4*>(&Kb[(long)(kb + c) * NHD + d4]);
            Ks[(d4 + 0) * 64 + c] = kv.x;
            Ks[(d4 + 1) * 64 + c] = kv.y;
            Ks[(d4 + 2) * 64 + c] = kv.z;
            Ks[(d4 + 3) * 64 + c] = kv.w;
            float4 vv = *reinterpret_cast<const float4*>(&Vb[(long)(kb + c) * NHD + d4]);
            *reinterpret_cast<float4*>(&Vs[c * 64 + d4]) = vv;
        }
        __syncthreads();

        float s[8][4];
#pragma unroll
        for (int i = 0; i < 8; i++)
#pragma unroll
            for (int j = 0; j < 4; j++) s[i][j] = 0.f;

#pragma unroll 8
        for (int d = 0; d < 64; d++) {
            float a[8], kx[4];
            *reinterpret_cast<float4*>(&a[0]) =
                *reinterpret_cast<const float4*>(&Qs[d * 128 + ty * 8]);
            *reinterpret_cast<float4*>(&a[4]) =
                *reinterpret_cast<const float4*>(&Qs[d * 128 + ty * 8 + 4]);
            *reinterpret_cast<float4*>(&kx[0]) =
                *reinterpret_cast<const float4*>(&Ks[d * 64 + tx * 4]);
#pragma unroll
            for (int i = 0; i < 8; i++)
#pragma unroll
                for (int j = 0; j < 4; j++)
                    s[i][j] = fmaf(a[i], kx[j], s[i][j]);
        }

#pragma unroll
        for (int i = 0; i < 8; i++) {
            float mb = fmaxf(fmaxf(s[i][0], s[i][1]), fmaxf(s[i][2], s[i][3]));
#pragma unroll
            for (int off = 8; off; off >>= 1)
                mb = fmaxf(mb, __shfl_xor_sync(0xffffffffu, mb, off));
            float mn = fmaxf(m[i], mb);
            float al = __expf(m[i] - mn);
            m[i] = mn;
            float p[4];
            float ps = 0.f;
#pragma unroll
            for (int j = 0; j < 4; j++) { p[j] = __expf(s[i][j] - mn); ps += p[j]; }
            *reinterpret_cast<float4*>(&Ps[(ty * 8 + i) * 64 + tx * 4]) =
                *reinterpret_cast<float4*>(p);
#pragma unroll
            for (int off = 8; off; off >>= 1)
                ps += __shfl_xor_sync(0xffffffffu, ps, off);
            l[i] = l[i] * al + ps;
#pragma unroll
            for (int j = 0; j < 4; j++) o[i][j] *= al;
        }
        __syncthreads();

#pragma unroll 8
        for (int kk = 0; kk < 64; kk++) {
            float vj[4];
            *reinterpret_cast<float4*>(&vj[0]) =
                *reinterpret_cast<const float4*>(&Vs[kk * 64 + tx * 4]);
#pragma unroll
            for (int i = 0; i < 8; i++) {
                float p = Ps[(ty * 8 + i) * 64 + kk];
#pragma unroll
                for (int j = 0; j < 4; j++)
                    o[i][j] = fmaf(p, vj[j], o[i][j]);
            }
        }
    }

    float* Xb = X + base + (long)q0 * NHD;
#pragma unroll
    for (int i = 0; i < 8; i++) {
        float inv = 1.f / l[i];
        float4 w;
        w.x = o[i][0] * inv; w.y = o[i][1] * inv;
        w.z = o[i][2] * inv; w.w = o[i][3] * inv;
        *reinterpret_cast<float4*>(&Xb[(long)(ty * 8 + i) * NHD + tx * 4]) = w;
    }
}

// ---------------------------------------------------------------------------
extern "C" void kernel_launch(void* const* d_in, const int* in_sizes, int n_in,
                              void* d_out, int out_size)
{
    const float* xq  = (const float*)d_in[0];
    const float* xkv = (const float*)d_in[1];
    const float* Wq  = (const float*)d_in[2];
    const float* bq  = (const float*)d_in[3];
    const float* Wk  = (const float*)d_in[4];
    const float* bk  = (const float*)d_in[5];
    const float* Wv  = (const float*)d_in[6];
    const float* bv  = (const float*)d_in[7];
    const float* Wo  = (const float*)d_in[8];
    const float* bo  = (const float*)d_in[9];
    float* out = (float*)d_out;

    float *qp, *kp, *vp, *xp;
    __nv_bfloat16 *aq, *akv, *ax, *bqW, *bkW, *bvW, *boW;
    cudaGetSymbolAddress((void**)&qp, g_Q);
    cudaGetSymbolAddress((void**)&kp, g_K);
    cudaGetSymbolAddress((void**)&vp, g_V);
    cudaGetSymbolAddress((void**)&xp, g_X);
    cudaGetSymbolAddress((void**)&aq, g_Aq);
    cudaGetSymbolAddress((void**)&akv, g_Akv);
    cudaGetSymbolAddress((void**)&ax, g_Ax);
    cudaGetSymbolAddress((void**)&bqW, g_Bq);
    cudaGetSymbolAddress((void**)&bkW, g_Bk);
    cudaGetSymbolAddress((void**)&bvW, g_Bv);
    cudaGetSymbolAddress((void**)&boW, g_Bo);

    // split conversions
    {
        int nb = (TOK * Dd / 4 + 255) / 256;
        split_act_kernel<<<nb, 256>>>(xq,  aq,  TOK, Dd);
        split_act_kernel<<<nb, 256>>>(xkv, akv, TOK, Dd);
    }
    {
        dim3 gw(NHD / 32, Dd / 32), bw(32, 32);
        split_wt_kernel<<<gw, bw>>>(Wq, bqW, Dd, NHD);
        split_wt_kernel<<<gw, bw>>>(Wk, bkW, Dd, NHD);
        split_wt_kernel<<<gw, bw>>>(Wv, bvW, Dd, NHD);
        split_wt_kernel<<<dim3(Dd / 32, NHD / 32), bw>>>(Wo, boW, NHD, Dd);
    }

    // HMMA GEMMs
    static const int GEMM_SMEM = NSTAGE * STAGE_BYTES;   // 61440
    cudaFuncSetAttribute(gemm_mma_kernel,
                         cudaFuncAttributeMaxDynamicSharedMemorySize, GEMM_SMEM);
    dim3 gg(NHD / 128, TOK / 128);                       // (8, 64)
    gemm_mma_kernel<<<gg, 256, GEMM_SMEM>>>(aq,  bqW, bq, qp, NHD, 0.125f);
    gemm_mma_kernel<<<gg, 256, GEMM_SMEM>>>(akv, bkW, bk, kp, NHD, 1.0f);
    gemm_mma_kernel<<<gg, 256, GEMM_SMEM>>>(akv, bvW, bv, vp, NHD, 1.0f);

    // attention (fp32)
    cudaFuncSetAttribute(flash_attn_kernel,
                         cudaFuncAttributeMaxDynamicSharedMemorySize, 98304);
    dim3 ga(Ss / 128, Bb * Hh);
    flash_attn_kernel<<<ga, 256, 98304>>>(qp, kp, vp, xp);

    // output projection
    {
        int nb = (TOK * NHD / 4 + 255) / 256;
        split_act_kernel<<<nb, 256>>>(xp, ax, TOK, NHD);
    }
    gemm_mma_kernel<<<gg, 256, GEMM_SMEM>>>(ax, boW, bo, out, Dd, 1.0f);
}

// round 16
// speedup vs baseline: 2.3503x; 1.7596x over previous
#include <cuda_runtime.h>
#include <cuda_bf16.h>
#include <cstdint>

// Problem constants
#define Bb 4
#define Ss 2048
#define Dd 1024
#define Hh 16
#define DHd 64
#define TOK (Bb*Ss)          // 8192
#define NHD (Hh*DHd)         // 1024
#define KP  3072             // split-K' = 3*1024
#define BH  (Bb*Hh)          // 64

// ---------------- scratch (device globals; no allocs allowed) ----------------
__device__ __nv_bfloat16 g_Aq [(size_t)TOK*KP];          // split input xq
__device__ __nv_bfloat16 g_Akv[(size_t)TOK*KP];          // split input xkv
__device__ __nv_bfloat16 g_Ax [(size_t)TOK*KP];          // split attn output (written by attn)
__device__ __nv_bfloat16 g_Bq [(size_t)NHD*KP];
__device__ __nv_bfloat16 g_Bk [(size_t)NHD*KP];
__device__ __nv_bfloat16 g_Bv [(size_t)NHD*KP];
__device__ __nv_bfloat16 g_Bo [(size_t)Dd*KP];
__device__ __nv_bfloat16 g_Qa [(size_t)BH*Ss*192];       // [bh][s][ Qh | Qh | Ql ]
__device__ __nv_bfloat16 g_Ka [(size_t)BH*Ss*192];       // [bh][s][ Kh | Kl | Kh ]
__device__ __nv_bfloat16 g_Vth[(size_t)BH*DHd*Ss];       // [bh][dh][s] hi
__device__ __nv_bfloat16 g_Vtl[(size_t)BH*DHd*Ss];       // [bh][dh][s] lo

// ---------------- helpers ----------------
__device__ __forceinline__ uint32_t smem_u32(const void* p) {
    uint32_t a;
    asm("{ .reg .u64 t; cvta.to.shared.u64 t, %1; cvt.u32.u64 %0, t; }" : "=r"(a) : "l"(p));
    return a;
}
__device__ __forceinline__ void cp_async16(uint32_t dst, const void* src) {
    asm volatile("cp.async.cg.shared.global [%0], [%1], 16;" :: "r"(dst), "l"(src) : "memory");
}
__device__ __forceinline__ void ldsm_x4(uint32_t* r, uint32_t addr) {
    asm volatile("ldmatrix.sync.aligned.m8n8.x4.shared.b16 {%0,%1,%2,%3}, [%4];"
                 : "=r"(r[0]), "=r"(r[1]), "=r"(r[2]), "=r"(r[3]) : "r"(addr));
}
__device__ __forceinline__ void mma16816(float* d, const uint32_t* a, uint32_t b0, uint32_t b1) {
    asm volatile(
        "mma.sync.aligned.m16n8k16.row.col.f32.bf16.bf16.f32 "
        "{%0,%1,%2,%3}, {%4,%5,%6,%7}, {%8,%9}, {%0,%1,%2,%3};"
        : "+f"(d[0]), "+f"(d[1]), "+f"(d[2]), "+f"(d[3])
        : "r"(a[0]), "r"(a[1]), "r"(a[2]), "r"(a[3]), "r"(b0), "r"(b1));
}
// split one fp32 value into bf16 hi + residual lo
__device__ __forceinline__ void bsplit(float v, __nv_bfloat16& h, __nv_bfloat16& l) {
    h = __float2bfloat16(v);
    l = __float2bfloat16(v - __bfloat162float(h));
}
__device__ __forceinline__ uint32_t packh(__nv_bfloat16 a, __nv_bfloat16 b) {
    return ((uint32_t)__bfloat16_as_ushort(b) << 16) | __bfloat16_as_ushort(a);
}

// ---------------------------------------------------------------------------
// split conversions:  fp32 X[M,K] -> bf16 A'[M,3K] = [hi | hi | lo]
// ---------------------------------------------------------------------------
__global__ void split_act_kernel(const float* __restrict__ X,
                                 __nv_bfloat16* __restrict__ P, int M, int K)
{
    long i = (long)blockIdx.x * blockDim.x + threadIdx.x;
    long total = (long)M * K / 4;
    if (i >= total) return;
    int m  = (int)(i / (K / 4));
    int k4 = (int)(i % (K / 4)) * 4;
    float4 v = *reinterpret_cast<const float4*>(&X[(long)m * K + k4]);
    __nv_bfloat16 h0, h1, h2, h3, l0, l1, l2, l3;
    bsplit(v.x, h0, l0); bsplit(v.y, h1, l1);
    bsplit(v.z, h2, l2); bsplit(v.w, h3, l3);
    uint2 hh, ll;
    hh.x = packh(h0, h1); hh.y = packh(h2, h3);
    ll.x = packh(l0, l1); ll.y = packh(l2, l3);
    long base = (long)m * (3 * K) + k4;
    *reinterpret_cast<uint2*>(&P[base])         = hh;
    *reinterpret_cast<uint2*>(&P[base + K])     = hh;
    *reinterpret_cast<uint2*>(&P[base + 2 * K]) = ll;
}

// fp32 W[K,N] -> bf16 B'[N,3K] = rows n: [Wh(:,n) | Wl(:,n) | Wh(:,n)]
__global__ void split_wt_kernel(const float* __restrict__ W,
                                __nv_bfloat16* __restrict__ P, int K, int N)
{
    __shared__ float sm[32][33];
    int n0 = blockIdx.x * 32, k0 = blockIdx.y * 32;
    int tx = threadIdx.x, ty = threadIdx.y;
    sm[ty][tx] = W[(long)(k0 + ty) * N + n0 + tx];
    __syncthreads();
    float v = sm[tx][ty];
    int n = n0 + ty, k = k0 + tx;
    __nv_bfloat16 h, l; bsplit(v, h, l);
    long base = (long)n * (3 * K);
    P[base + k]         = h;
    P[base + K + k]     = l;
    P[base + 2 * K + k] = h;
}

// ---------------------------------------------------------------------------
// HMMA GEMM: acc = A'[M,3K] @ B'[N,3K]^T ; epilogue v = alpha*(acc+bias)
// MODE 0: fp32 C[M,N]
// MODE 1: Q-layout g_Qa [bh][s][192] = [hi|hi|lo]
// MODE 2: K-layout g_Ka [bh][s][192] = [hi|lo|hi]
// MODE 3: Vt-layout g_Vth/g_Vtl [bh][dh][s]
// ---------------------------------------------------------------------------
#define GSTRIDE 40
#define STAGE_BYTES (2 * 128 * GSTRIDE * 2)
#define NSTAGE 3

template<int MODE>
__global__ __launch_bounds__(256, 2)
void gemm_mma_kernel(const __nv_bfloat16* __restrict__ A,
                     const __nv_bfloat16* __restrict__ Bp,
                     const float* __restrict__ bias, float* __restrict__ C,
                     __nv_bfloat16* __restrict__ O1, __nv_bfloat16* __restrict__ O2,
                     int N, float alpha)
{
    constexpr int NIT = KP / 32;         // 96
    extern __shared__ char smem[];
    const uint32_t smb = smem_u32(smem);

    const int tid  = threadIdx.x;
    const int lane = tid & 31, w = tid >> 5;
    const int wm = (w & 3) * 32;
    const int wn = (w >> 2) * 64;
    const int bm = blockIdx.y * 128, bn = blockIdx.x * 128;

    const __nv_bfloat16* Abase = A  + (size_t)bm * KP;
    const __nv_bfloat16* Bbase = Bp + (size_t)bn * KP;

    auto load_stage = [&](int st) {
        uint32_t base = smb + (uint32_t)(st % NSTAGE) * STAGE_BYTES;
        int k0 = st * 32;
#pragma unroll
        for (int j = 0; j < 2; j++) {
            int c = tid + 256 * j;
            int row = c >> 2, cc = (c & 3);
            cp_async16(base + row * (GSTRIDE * 2) + cc * 16,
                       Abase + (size_t)row * KP + k0 + cc * 8);
        }
#pragma unroll
        for (int j = 0; j < 2; j++) {
            int c = tid + 256 * j;
            int row = c >> 2, cc = (c & 3);
            cp_async16(base + 128 * (GSTRIDE * 2) + row * (GSTRIDE * 2) + cc * 16,
                       Bbase + (size_t)row * KP + k0 + cc * 8);
        }
    };

    float acc[2][8][4];
#pragma unroll
    for (int mi = 0; mi < 2; mi++)
#pragma unroll
        for (int ni = 0; ni < 8; ni++)
#pragma unroll
            for (int j = 0; j < 4; j++) acc[mi][ni][j] = 0.f;

    load_stage(0); asm volatile("cp.async.commit_group;" ::: "memory");
    load_stage(1); asm volatile("cp.async.commit_group;" ::: "memory");

    const uint32_t a_row = (lane & 15);
    const uint32_t a_kof = ((lane >> 4) & 1) * 8;
    const uint32_t b_row = ((lane >> 4) & 1) * 8 + (lane & 7);
    const uint32_t b_kof = ((lane >> 3) & 1) * 8;

    for (int kt = 0; kt < NIT; kt++) {
        asm volatile("cp.async.wait_group %0;" :: "n"(NSTAGE - 2) : "memory");
        __syncthreads();
        if (kt + NSTAGE - 1 < NIT) load_stage(kt + NSTAGE - 1);
        asm volatile("cp.async.commit_group;" ::: "memory");

        uint32_t sa = smb + (uint32_t)(kt % NSTAGE) * STAGE_BYTES;
        uint32_t sb = sa + 128 * (GSTRIDE * 2);
#pragma unroll
        for (int kh = 0; kh < 2; kh++) {
            int k16 = kh * 16;
            uint32_t a[2][4], b[4][4];
#pragma unroll
            for (int mi = 0; mi < 2; mi++)
                ldsm_x4(a[mi], sa + (wm + mi * 16 + a_row) * (GSTRIDE * 2)
                               + (k16 + a_kof) * 2);
#pragma unroll
            for (int nq = 0; nq < 4; nq++)
                ldsm_x4(b[nq], sb + (wn + nq * 16 + b_row) * (GSTRIDE * 2)
                               + (k16 + b_kof) * 2);
#pragma unroll
            for (int mi = 0; mi < 2; mi++)
#pragma unroll
                for (int ni = 0; ni < 8; ni++)
                    mma16816(acc[mi][ni], a[mi],
                             b[ni >> 1][(ni & 1) * 2],
                             b[ni >> 1][(ni & 1) * 2 + 1]);
        }
        __syncthreads();
    }

    // epilogue
    const int r0 = lane >> 2;
    const int c0 = (lane & 3) * 2;
#pragma unroll
    for (int mi = 0; mi < 2; mi++) {
        int growb = bm + wm + mi * 16 + r0;
#pragma unroll
        for (int ni = 0; ni < 8; ni++) {
            int gcol = bn + wn + ni * 8 + c0;
            float b0 = __ldg(bias + gcol), b1 = __ldg(bias + gcol + 1);
            float v00 = alpha * (acc[mi][ni][0] + b0);
            float v01 = alpha * (acc[mi][ni][1] + b1);
            float v10 = alpha * (acc[mi][ni][2] + b0);
            float v11 = alpha * (acc[mi][ni][3] + b1);
            if (MODE == 0) {
                float2 o0 = {v00, v01}, o1 = {v10, v11};
                *reinterpret_cast<float2*>(&C[(size_t)growb * N + gcol]) = o0;
                *reinterpret_cast<float2*>(&C[(size_t)(growb + 8) * N + gcol]) = o1;
            } else {
                int h = gcol >> 6, dh = gcol & 63;
                if (MODE == 1 || MODE == 2) {
#pragma unroll
                    for (int rr = 0; rr < 2; rr++) {
                        int grow = growb + rr * 8;
                        int s = grow & 2047, bidx = grow >> 11;
                        size_t base = ((size_t)(bidx * 16 + h) * 2048 + s) * 192 + dh;
                        float x0 = rr ? v10 : v00, x1 = rr ? v11 : v01;
                        __nv_bfloat16 h0, l0, h1, l1;
                        bsplit(x0, h0, l0); bsplit(x1, h1, l1);
                        uint32_t hp = packh(h0, h1), lp = packh(l0, l1);
                        if (MODE == 1) {
                            *reinterpret_cast<uint32_t*>(&O1[base])       = hp;
                            *reinterpret_cast<uint32_t*>(&O1[base + 64])  = hp;
                            *reinterpret_cast<uint32_t*>(&O1[base + 128]) = lp;
                        } else {
                            *reinterpret_cast<uint32_t*>(&O1[base])       = hp;
                            *reinterpret_cast<uint32_t*>(&O1[base + 64])  = lp;
                            *reinterpret_cast<uint32_t*>(&O1[base + 128]) = hp;
                        }
                    }
                } else {  // MODE 3 : Vt [bh][dh][s]
#pragma unroll
                    for (int rr = 0; rr < 2; rr++) {
                        int grow = growb + rr * 8;
                        int s = grow & 2047, bidx = grow >> 11;
                        size_t vb = ((size_t)(bidx * 16 + h) * 64) * 2048 + s;
                        float x0 = rr ? v10 : v00, x1 = rr ? v11 : v01;
                        __nv_bfloat16 h0, l0, h1, l1;
                        bsplit(x0, h0, l0); bsplit(x1, h1, l1);
                        O1[vb + (size_t)dh * 2048]       = h0;
                        O2[vb + (size_t)dh * 2048]       = l0;
                        O1[vb + (size_t)(dh + 1) * 2048] = h1;
                        O2[vb + (size_t)(dh + 1) * 2048] = l1;
                    }
                }
            }
        }
    }
}

// ---------------------------------------------------------------------------
// MMA flash attention.
// CTA: one (bh, 128-q tile). 8 warps, each m16. Key tiles BN=128.
// Q' frags (k=192) in registers. Double-buffered K'/Vt tiles via cp.async.
// Scores use exp2 (log2e folded into Q scale). PV = PhVh + PhVl + PlVh.
// Output written to g_Ax as [hi|hi|lo] rows for the out-projection GEMM.
// ---------------------------------------------------------------------------
#define QSTR 200                          // halfs per K'/Q' smem row
#define VSTR 136                          // halfs per Vt smem row
#define KBYTES (128 * QSTR * 2)           // 51200
#define VBYTES (64 * VSTR * 2)            // 17408
#define ABUF   (KBYTES + 2 * VBYTES)      // 86016
#define ATTN_SMEM (2 * ABUF)              // 172032

__global__ __launch_bounds__(256)
void attn_mma_kernel(const __nv_bfloat16* __restrict__ Qa,
                     const __nv_bfloat16* __restrict__ Ka,
                     const __nv_bfloat16* __restrict__ Vh,
                     const __nv_bfloat16* __restrict__ Vl,
                     __nv_bfloat16* __restrict__ Ax)
{
    extern __shared__ char smem[];
    const uint32_t smb = smem_u32(smem);
    const int tid = threadIdx.x, lane = tid & 31, w = tid >> 5;
    const int bh = blockIdx.y;
    const int q0 = blockIdx.x * 128;
    const int wq = w * 16;

    const __nv_bfloat16* Qg  = Qa + ((size_t)bh * 2048 + q0) * 192;
    const __nv_bfloat16* Kg  = Ka + (size_t)bh * 2048 * 192;
    const __nv_bfloat16* Vhg = Vh + (size_t)bh * 64 * 2048;
    const __nv_bfloat16* Vlg = Vl + (size_t)bh * 64 * 2048;

    const uint32_t a_row = lane & 15, a_kof = ((lane >> 4) & 1) * 8;
    const uint32_t b_row = ((lane >> 4) & 1) * 8 + (lane & 7);
    const uint32_t b_kof = ((lane >> 3) & 1) * 8;
    const int r0 = lane >> 2, c0 = (lane & 3) * 2;

    auto load_tile = [&](int kt) {
        uint32_t bb = smb + (uint32_t)(kt & 1) * ABUF;
        int k0 = kt * 128;
#pragma unroll
        for (int j = 0; j < 12; j++) {          // K' tile: 128 x 192 halfs
            int c = tid + 256 * j;
            int row = c / 24, cc = c % 24;
            cp_async16(bb + row * (QSTR * 2) + cc * 16,
                       Kg + ((size_t)(k0 + row)) * 192 + cc * 8);
        }
#pragma unroll
        for (int j = 0; j < 4; j++) {           // Vt hi: 64 x 128 halfs
            int c = tid + 256 * j;
            int row = c >> 4, cc = c & 15;
            cp_async16(bb + KBYTES + row * (VSTR * 2) + cc * 16,
                       Vhg + (size_t)row * 2048 + k0 + cc * 8);
        }
#pragma unroll
        for (int j = 0; j < 4; j++) {           // Vt lo
            int c = tid + 256 * j;
            int row = c >> 4, cc = c & 15;
            cp_async16(bb + KBYTES + VBYTES + row * (VSTR * 2) + cc * 16,
                       Vlg + (size_t)row * 2048 + k0 + cc * 8);
        }
    };

    // prologue: Q' tile into buf1, tile0 into buf0
#pragma unroll
    for (int j = 0; j < 12; j++) {
        int c = tid + 256 * j;
        int row = c / 24, cc = c % 24;
        cp_async16(smb + ABUF + row * (QSTR * 2) + cc * 16,
                   Qg + (size_t)row * 192 + cc * 8);
    }
    asm volatile("cp.async.commit_group;" ::: "memory");
    load_tile(0);
    asm volatile("cp.async.commit_group;" ::: "memory");
    asm volatile("cp.async.wait_group 1;" ::: "memory");   // Q resident
    __syncthreads();

    uint32_t q[12][4];
#pragma unroll
    for (int ks = 0; ks < 12; ks++)
        ldsm_x4(q[ks], smb + ABUF + (wq + a_row) * (QSTR * 2) + (ks * 16 + a_kof) * 2);
    __syncthreads();                                       // buf1 free for tile1

    float o[8][4];
#pragma unroll
    for (int f = 0; f < 8; f++)
#pragma unroll
        for (int j = 0; j < 4; j++) o[f][j] = 0.f;
    float m2[2] = {-1e30f, -1e30f}, l2[2] = {0.f, 0.f};

    for (int kt = 0; kt < 16; kt++) {
        if (kt < 15) load_tile(kt + 1);
        asm volatile("cp.async.commit_group;" ::: "memory");
        if (kt < 15) asm volatile("cp.async.wait_group 1;" ::: "memory");
        else         asm volatile("cp.async.wait_group 0;" ::: "memory");
        __syncthreads();

        uint32_t kb = smb + (uint32_t)(kt & 1) * ABUF;

        // ---- S = Q' K'^T  (16 n8-frags, 12 k16 steps) ----
        float sacc[16][4];
#pragma unroll
        for (int f = 0; f < 16; f++)
#pragma unroll
            for (int j = 0; j < 4; j++) sacc[f][j] = 0.f;
#pragma unroll
        for (int ks = 0; ks < 12; ks++) {
#pragma unroll
            for (int nq = 0; nq < 8; nq++) {
                uint32_t bf[4];
                ldsm_x4(bf, kb + (nq * 16 + b_row) * (QSTR * 2) + (ks * 16 + b_kof) * 2);
                mma16816(sacc[2 * nq],     q[ks], bf[0], bf[1]);
                mma16816(sacc[2 * nq + 1], q[ks], bf[2], bf[3]);
            }
        }

        // ---- online softmax (base-2; Q pre-scaled by 0.125*log2e) ----
#pragma unroll
        for (int rh = 0; rh < 2; rh++) {
            float mt = -1e30f;
#pragma unroll
            for (int f = 0; f < 16; f++)
                mt = fmaxf(mt, fmaxf(sacc[f][2 * rh], sacc[f][2 * rh + 1]));
            mt = fmaxf(mt, __shfl_xor_sync(0xffffffffu, mt, 1));
            mt = fmaxf(mt, __shfl_xor_sync(0xffffffffu, mt, 2));
            float mn = fmaxf(m2[rh], mt);
            float sc = exp2f(m2[rh] - mn);
            m2[rh] = mn;
            float rs = 0.f;
#pragma unroll
            for (int f = 0; f < 16; f++) {
                float p0 = exp2f(sacc[f][2 * rh] - mn);
                float p1 = exp2f(sacc[f][2 * rh + 1] - mn);
                sacc[f][2 * rh] = p0; sacc[f][2 * rh + 1] = p1;
                rs += p0 + p1;
            }
            rs += __shfl_xor_sync(0xffffffffu, rs, 1);
            rs += __shfl_xor_sync(0xffffffffu, rs, 2);
            l2[rh] = l2[rh] * sc + rs;
#pragma unroll
            for (int f = 0; f < 8; f++) {
                o[f][2 * rh] *= sc; o[f][2 * rh + 1] *= sc;
            }
        }

        // ---- O += Ph Vh + Ph Vl + Pl Vh ----
        uint32_t vhb = kb + KBYTES, vlb = vhb + VBYTES;
#pragma unroll
        for (int kf = 0; kf < 8; kf++) {
            uint32_t ah[4], al[4];
#pragma unroll
            for (int jj = 0; jj < 2; jj++) {          // jj=0 -> frag 2kf (k0-7), jj=1 -> 2kf+1 (k8-15)
                float* p = sacc[2 * kf + jj];
                __nv_bfloat16 h0, l0, h1, l1, h2, l3h, h3, l3;
                bsplit(p[0], h0, l0); bsplit(p[1], h1, l1);
                ah[jj * 2]     = packh(h0, h1);
                al[jj * 2]     = packh(l0, l1);
                bsplit(p[2], h2, l3h); bsplit(p[3], h3, l3);
                ah[jj * 2 + 1] = packh(h2, h3);
                al[jj * 2 + 1] = packh(l3h, l3);
            }
#pragma unroll
            for (int ng = 0; ng < 4; ng++) {
                uint32_t bh4[4], bl4[4];
                ldsm_x4(bh4, vhb + (ng * 16 + b_row) * (VSTR * 2) + (kf * 16 + b_kof) * 2);
                ldsm_x4(bl4, vlb + (ng * 16 + b_row) * (VSTR * 2) + (kf * 16 + b_kof) * 2);
                mma16816(o[2 * ng],     ah, bh4[0], bh4[1]);
                mma16816(o[2 * ng + 1], ah, bh4[2], bh4[3]);
                mma16816(o[2 * ng],     ah, bl4[0], bl4[1]);
                mma16816(o[2 * ng + 1], ah, bl4[2], bl4[3]);
                mma16816(o[2 * ng],     al, bh4[0], bh4[1]);
                mma16816(o[2 * ng + 1], al, bh4[2], bh4[3]);
            }
        }
        __syncthreads();   // compute done before next-next buffer overwrite
    }

    // ---- epilogue: x = O/l, write [hi|hi|lo] rows of g_Ax ----
    const int b = bh >> 4, h = bh & 15;
    float inv0 = 1.f / l2[0], inv1 = 1.f / l2[1];
#pragma unroll
    for (int f = 0; f < 8; f++) {
        int col = h * 64 + f * 8 + c0;
#pragma unroll
        for (int rh = 0; rh < 2; rh++) {
            int gq = q0 + wq + r0 + rh * 8;
            size_t base = (size_t)(b * 2048 + gq) * 3072 + col;
            float inv = rh ? inv1 : inv0;
            float x0 = o[f][2 * rh] * inv, x1 = o[f][2 * rh + 1] * inv;
            __nv_bfloat16 h0, l0, h1, l1;
            bsplit(x0, h0, l0); bsplit(x1, h1, l1);
            uint32_t hp = packh(h0, h1), lp = packh(l0, l1);
            *reinterpret_cast<uint32_t*>(&Ax[base])        = hp;
            *reinterpret_cast<uint32_t*>(&Ax[base + 1024]) = hp;
            *reinterpret_cast<uint32_t*>(&Ax[base + 2048]) = lp;
        }
    }
}

// ---------------------------------------------------------------------------
extern "C" void kernel_launch(void* const* d_in, const int* in_sizes, int n_in,
                              void* d_out, int out_size)
{
    const float* xq  = (const float*)d_in[0];
    const float* xkv = (const float*)d_in[1];
    const float* Wq  = (const float*)d_in[2];
    const float* bq  = (const float*)d_in[3];
    const float* Wk  = (const float*)d_in[4];
    const float* bk  = (const float*)d_in[5];
    const float* Wv  = (const float*)d_in[6];
    const float* bv  = (const float*)d_in[7];
    const float* Wo  = (const float*)d_in[8];
    const float* bo  = (const float*)d_in[9];
    float* out = (float*)d_out;

    __nv_bfloat16 *aq, *akv, *ax, *bqW, *bkW, *bvW, *boW, *qa, *ka, *vth, *vtl;
    cudaGetSymbolAddress((void**)&aq,  g_Aq);
    cudaGetSymbolAddress((void**)&akv, g_Akv);
    cudaGetSymbolAddress((void**)&ax,  g_Ax);
    cudaGetSymbolAddress((void**)&bqW, g_Bq);
    cudaGetSymbolAddress((void**)&bkW, g_Bk);
    cudaGetSymbolAddress((void**)&bvW, g_Bv);
    cudaGetSymbolAddress((void**)&boW, g_Bo);
    cudaGetSymbolAddress((void**)&qa,  g_Qa);
    cudaGetSymbolAddress((void**)&ka,  g_Ka);
    cudaGetSymbolAddress((void**)&vth, g_Vth);
    cudaGetSymbolAddress((void**)&vtl, g_Vtl);

    // input splits
    {
        int nb = (TOK * Dd / 4 + 255) / 256;
        split_act_kernel<<<nb, 256>>>(xq,  aq,  TOK, Dd);
        split_act_kernel<<<nb, 256>>>(xkv, akv, TOK, Dd);
    }
    {
        dim3 gw(NHD / 32, Dd / 32), bw(32, 32);
        split_wt_kernel<<<gw, bw>>>(Wq, bqW, Dd, NHD);
        split_wt_kernel<<<gw, bw>>>(Wk, bkW, Dd, NHD);
        split_wt_kernel<<<gw, bw>>>(Wv, bvW, Dd, NHD);
        split_wt_kernel<<<dim3(Dd / 32, NHD / 32), bw>>>(Wo, boW, NHD, Dd);
    }

    static const int GEMM_SMEM = NSTAGE * STAGE_BYTES;   // 61440
    cudaFuncSetAttribute(gemm_mma_kernel<0>, cudaFuncAttributeMaxDynamicSharedMemorySize, GEMM_SMEM);
    cudaFuncSetAttribute(gemm_mma_kernel<1>, cudaFuncAttributeMaxDynamicSharedMemorySize, GEMM_SMEM);
    cudaFuncSetAttribute(gemm_mma_kernel<2>, cudaFuncAttributeMaxDynamicSharedMemorySize, GEMM_SMEM);
    cudaFuncSetAttribute(gemm_mma_kernel<3>, cudaFuncAttributeMaxDynamicSharedMemorySize, GEMM_SMEM);
    cudaFuncSetAttribute(attn_mma_kernel,    cudaFuncAttributeMaxDynamicSharedMemorySize, ATTN_SMEM);

    dim3 gg(NHD / 128, TOK / 128);                       // (8, 64)
    const float ALPHA_Q = 0.125f * 1.4426950408889634f;  // 1/sqrt(64) * log2(e)

    // projections -> attention layouts
    gemm_mma_kernel<1><<<gg, 256, GEMM_SMEM>>>(aq,  bqW, bq, nullptr, qa,  nullptr, NHD, ALPHA_Q);
    gemm_mma_kernel<2><<<gg, 256, GEMM_SMEM>>>(akv, bkW, bk, nullptr, ka,  nullptr, NHD, 1.0f);
    gemm_mma_kernel<3><<<gg, 256, GEMM_SMEM>>>(akv, bvW, bv, nullptr, vth, vtl,     NHD, 1.0f);

    // attention (tensor-core) -> g_Ax (pre-split for out projection)
    dim3 ga(Ss / 128, BH);                               // (16, 64)
    attn_mma_kernel<<<ga, 256, ATTN_SMEM>>>(qa, ka, vth, vtl, ax);

    // output projection
    gemm_mma_kernel<0><<<gg, 256, GEMM_SMEM>>>(ax, boW, bo, out, nullptr, nullptr, Dd, 1.0f);
}

// round 17
// speedup vs baseline: 2.3510x; 1.0003x over previous
#include <cuda_runtime.h>
#include <cuda_bf16.h>
#include <cstdint>

// Problem constants
#define Bb 4
#define Ss 2048
#define Dd 1024
#define Hh 16
#define DHd 64
#define TOK (Bb*Ss)          // 8192
#define NHD (Hh*DHd)         // 1024
#define KP  3072             // split-K' = 3*1024
#define BH  (Bb*Hh)          // 64

// ---------------- scratch (device globals; no allocs allowed) ----------------
__device__ __nv_bfloat16 g_Aq [(size_t)TOK*KP];          // split input xq
__device__ __nv_bfloat16 g_Akv[(size_t)TOK*KP];          // split input xkv
__device__ __nv_bfloat16 g_Ax [(size_t)TOK*KP];          // split attn output (written by attn)
__device__ __nv_bfloat16 g_Bq [(size_t)NHD*KP];
__device__ __nv_bfloat16 g_Bk [(size_t)NHD*KP];
__device__ __nv_bfloat16 g_Bv [(size_t)NHD*KP];
__device__ __nv_bfloat16 g_Bo [(size_t)Dd*KP];
__device__ __nv_bfloat16 g_Qa [(size_t)BH*Ss*192];       // [bh][s][ Qh | Qh | Ql ]
__device__ __nv_bfloat16 g_Ka [(size_t)BH*Ss*192];       // [bh][s][ Kh | Kl | Kh ]
__device__ __nv_bfloat16 g_Vth[(size_t)BH*DHd*Ss];       // [bh][dh][s] hi
__device__ __nv_bfloat16 g_Vtl[(size_t)BH*DHd*Ss];       // [bh][dh][s] lo

// ---------------- helpers ----------------
__device__ __forceinline__ uint32_t smem_u32(const void* p) {
    uint32_t a;
    asm("{ .reg .u64 t; cvta.to.shared.u64 t, %1; cvt.u32.u64 %0, t; }" : "=r"(a) : "l"(p));
    return a;
}
__device__ __forceinline__ void cp_async16(uint32_t dst, const void* src) {
    asm volatile("cp.async.cg.shared.global [%0], [%1], 16;" :: "r"(dst), "l"(src) : "memory");
}
__device__ __forceinline__ void ldsm_x4(uint32_t* r, uint32_t addr) {
    asm volatile("ldmatrix.sync.aligned.m8n8.x4.shared.b16 {%0,%1,%2,%3}, [%4];"
                 : "=r"(r[0]), "=r"(r[1]), "=r"(r[2]), "=r"(r[3]) : "r"(addr));
}
__device__ __forceinline__ void mma16816(float* d, const uint32_t* a, uint32_t b0, uint32_t b1) {
    asm volatile(
        "mma.sync.aligned.m16n8k16.row.col.f32.bf16.bf16.f32 "
        "{%0,%1,%2,%3}, {%4,%5,%6,%7}, {%8,%9}, {%0,%1,%2,%3};"
        : "+f"(d[0]), "+f"(d[1]), "+f"(d[2]), "+f"(d[3])
        : "r"(a[0]), "r"(a[1]), "r"(a[2]), "r"(a[3]), "r"(b0), "r"(b1));
}
// split one fp32 value into bf16 hi + residual lo
__device__ __forceinline__ void bsplit(float v, __nv_bfloat16& h, __nv_bfloat16& l) {
    h = __float2bfloat16(v);
    l = __float2bfloat16(v - __bfloat162float(h));
}
__device__ __forceinline__ uint32_t packh(__nv_bfloat16 a, __nv_bfloat16 b) {
    return ((uint32_t)__bfloat16_as_ushort(b) << 16) | __bfloat16_as_ushort(a);
}

// ---------------------------------------------------------------------------
// split conversions:  fp32 X[M,K] -> bf16 A'[M,3K] = [hi | hi | lo]
// ---------------------------------------------------------------------------
__global__ void split_act_kernel(const float* __restrict__ X,
                                 __nv_bfloat16* __restrict__ P, int M, int K)
{
    long i = (long)blockIdx.x * blockDim.x + threadIdx.x;
    long total = (long)M * K / 4;
    if (i >= total) return;
    int m  = (int)(i / (K / 4));
    int k4 = (int)(i % (K / 4)) * 4;
    float4 v = *reinterpret_cast<const float4*>(&X[(long)m * K + k4]);
    __nv_bfloat16 h0, h1, h2, h3, l0, l1, l2, l3;
    bsplit(v.x, h0, l0); bsplit(v.y, h1, l1);
    bsplit(v.z, h2, l2); bsplit(v.w, h3, l3);
    uint2 hh, ll;
    hh.x = packh(h0, h1); hh.y = packh(h2, h3);
    ll.x = packh(l0, l1); ll.y = packh(l2, l3);
    long base = (long)m * (3 * K) + k4;
    *reinterpret_cast<uint2*>(&P[base])         = hh;
    *reinterpret_cast<uint2*>(&P[base + K])     = hh;
    *reinterpret_cast<uint2*>(&P[base + 2 * K]) = ll;
}

// fp32 W[K,N] -> bf16 B'[N,3K] = rows n: [Wh(:,n) | Wl(:,n) | Wh(:,n)]
__global__ void split_wt_kernel(const float* __restrict__ W,
                                __nv_bfloat16* __restrict__ P, int K, int N)
{
    __shared__ float sm[32][33];
    int n0 = blockIdx.x * 32, k0 = blockIdx.y * 32;
    int tx = threadIdx.x, ty = threadIdx.y;
    sm[ty][tx] = W[(long)(k0 + ty) * N + n0 + tx];
    __syncthreads();
    float v = sm[tx][ty];
    int n = n0 + ty, k = k0 + tx;
    __nv_bfloat16 h, l; bsplit(v, h, l);
    long base = (long)n * (3 * K);
    P[base + k]         = h;
    P[base + K + k]     = l;
    P[base + 2 * K + k] = h;
}

// ---------------------------------------------------------------------------
// HMMA GEMM: acc = A'[M,3K] @ B'[N,3K]^T ; epilogue v = alpha*(acc+bias)
// MODE 0: fp32 C[M,N]
// MODE 1: Q-layout g_Qa [bh][s][192] = [hi|hi|lo]
// MODE 2: K-layout g_Ka [bh][s][192] = [hi|lo|hi]
// MODE 3: Vt-layout g_Vth/g_Vtl [bh][dh][s]
// ---------------------------------------------------------------------------
#define GSTRIDE 40
#define STAGE_BYTES (2 * 128 * GSTRIDE * 2)
#define NSTAGE 3

template<int MODE>
__global__ __launch_bounds__(256, 2)
void gemm_mma_kernel(const __nv_bfloat16* __restrict__ A,
                     const __nv_bfloat16* __restrict__ Bp,
                     const float* __restrict__ bias, float* __restrict__ C,
                     __nv_bfloat16* __restrict__ O1, __nv_bfloat16* __restrict__ O2,
                     int N, float alpha)
{
    constexpr int NIT = KP / 32;         // 96
    extern __shared__ char smem[];
    const uint32_t smb = smem_u32(smem);

    const int tid  = threadIdx.x;
    const int lane = tid & 31, w = tid >> 5;
    const int wm = (w & 3) * 32;
    const int wn = (w >> 2) * 64;
    const int bm = blockIdx.y * 128, bn = blockIdx.x * 128;

    const __nv_bfloat16* Abase = A  + (size_t)bm * KP;
    const __nv_bfloat16* Bbase = Bp + (size_t)bn * KP;

    auto load_stage = [&](int st) {
        uint32_t base = smb + (uint32_t)(st % NSTAGE) * STAGE_BYTES;
        int k0 = st * 32;
#pragma unroll
        for (int j = 0; j < 2; j++) {
            int c = tid + 256 * j;
            int row = c >> 2, cc = (c & 3);
            cp_async16(base + row * (GSTRIDE * 2) + cc * 16,
                       Abase + (size_t)row * KP + k0 + cc * 8);
        }
#pragma unroll
        for (int j = 0; j < 2; j++) {
            int c = tid + 256 * j;
            int row = c >> 2, cc = (c & 3);
            cp_async16(base + 128 * (GSTRIDE * 2) + row * (GSTRIDE * 2) + cc * 16,
                       Bbase + (size_t)row * KP + k0 + cc * 8);
        }
    };

    float acc[2][8][4];
#pragma unroll
    for (int mi = 0; mi < 2; mi++)
#pragma unroll
        for (int ni = 0; ni < 8; ni++)
#pragma unroll
            for (int j = 0; j < 4; j++) acc[mi][ni][j] = 0.f;

    load_stage(0); asm volatile("cp.async.commit_group;" ::: "memory");
    load_stage(1); asm volatile("cp.async.commit_group;" ::: "memory");

    const uint32_t a_row = (lane & 15);
    const uint32_t a_kof = ((lane >> 4) & 1) * 8;
    const uint32_t b_row = ((lane >> 4) & 1) * 8 + (lane & 7);
    const uint32_t b_kof = ((lane >> 3) & 1) * 8;

    for (int kt = 0; kt < NIT; kt++) {
        asm volatile("cp.async.wait_group %0;" :: "n"(NSTAGE - 2) : "memory");
        __syncthreads();
        if (kt + NSTAGE - 1 < NIT) load_stage(kt + NSTAGE - 1);
        asm volatile("cp.async.commit_group;" ::: "memory");

        uint32_t sa = smb + (uint32_t)(kt % NSTAGE) * STAGE_BYTES;
        uint32_t sb = sa + 128 * (GSTRIDE * 2);
#pragma unroll
        for (int kh = 0; kh < 2; kh++) {
            int k16 = kh * 16;
            uint32_t a[2][4], b[4][4];
#pragma unroll
            for (int mi = 0; mi < 2; mi++)
                ldsm_x4(a[mi], sa + (wm + mi * 16 + a_row) * (GSTRIDE * 2)
                               + (k16 + a_kof) * 2);
#pragma unroll
            for (int nq = 0; nq < 4; nq++)
                ldsm_x4(b[nq], sb + (wn + nq * 16 + b_row) * (GSTRIDE * 2)
                               + (k16 + b_kof) * 2);
#pragma unroll
            for (int mi = 0; mi < 2; mi++)
#pragma unroll
                for (int ni = 0; ni < 8; ni++)
                    mma16816(acc[mi][ni], a[mi],
                             b[ni >> 1][(ni & 1) * 2],
                             b[ni >> 1][(ni & 1) * 2 + 1]);
        }
        __syncthreads();
    }

    // epilogue
    const int r0 = lane >> 2;
    const int c0 = (lane & 3) * 2;
#pragma unroll
    for (int mi = 0; mi < 2; mi++) {
        int growb = bm + wm + mi * 16 + r0;
#pragma unroll
        for (int ni = 0; ni < 8; ni++) {
            int gcol = bn + wn + ni * 8 + c0;
            float b0 = __ldg(bias + gcol), b1 = __ldg(bias + gcol + 1);
            float v00 = alpha * (acc[mi][ni][0] + b0);
            float v01 = alpha * (acc[mi][ni][1] + b1);
            float v10 = alpha * (acc[mi][ni][2] + b0);
            float v11 = alpha * (acc[mi][ni][3] + b1);
            if (MODE == 0) {
                float2 o0 = {v00, v01}, o1 = {v10, v11};
                *reinterpret_cast<float2*>(&C[(size_t)growb * N + gcol]) = o0;
                *reinterpret_cast<float2*>(&C[(size_t)(growb + 8) * N + gcol]) = o1;
            } else {
                int h = gcol >> 6, dh = gcol & 63;
                if (MODE == 1 || MODE == 2) {
#pragma unroll
                    for (int rr = 0; rr < 2; rr++) {
                        int grow = growb + rr * 8;
                        int s = grow & 2047, bidx = grow >> 11;
                        size_t base = ((size_t)(bidx * 16 + h) * 2048 + s) * 192 + dh;
                        float x0 = rr ? v10 : v00, x1 = rr ? v11 : v01;
                        __nv_bfloat16 h0, l0, h1, l1;
                        bsplit(x0, h0, l0); bsplit(x1, h1, l1);
                        uint32_t hp = packh(h0, h1), lp = packh(l0, l1);
                        if (MODE == 1) {
                            *reinterpret_cast<uint32_t*>(&O1[base])       = hp;
                            *reinterpret_cast<uint32_t*>(&O1[base + 64])  = hp;
                            *reinterpret_cast<uint32_t*>(&O1[base + 128]) = lp;
                        } else {
                            *reinterpret_cast<uint32_t*>(&O1[base])       = hp;
                            *reinterpret_cast<uint32_t*>(&O1[base + 64])  = lp;
                            *reinterpret_cast<uint32_t*>(&O1[base + 128]) = hp;
                        }
                    }
                } else {  // MODE 3 : Vt [bh][dh][s]
#pragma unroll
                    for (int rr = 0; rr < 2; rr++) {
                        int grow = growb + rr * 8;
                        int s = grow & 2047, bidx = grow >> 11;
                        size_t vb = ((size_t)(bidx * 16 + h) * 64) * 2048 + s;
                        float x0 = rr ? v10 : v00, x1 = rr ? v11 : v01;
                        __nv_bfloat16 h0, l0, h1, l1;
                        bsplit(x0, h0, l0); bsplit(x1, h1, l1);
                        O1[vb + (size_t)dh * 2048]       = h0;
                        O2[vb + (size_t)dh * 2048]       = l0;
                        O1[vb + (size_t)(dh + 1) * 2048] = h1;
                        O2[vb + (size_t)(dh + 1) * 2048] = l1;
                    }
                }
            }
        }
    }
}

// ---------------------------------------------------------------------------
// MMA flash attention.
// CTA: one (bh, 128-q tile). 8 warps, each m16. Key tiles BN=128.
// Q' frags (k=192) in registers. Double-buffered K'/Vt tiles via cp.async.
// Scores use exp2 (log2e folded into Q scale). PV = PhVh + PhVl + PlVh.
// Output written to g_Ax as [hi|hi|lo] rows for the out-projection GEMM.
// ---------------------------------------------------------------------------
#define QSTR 200                          // halfs per K'/Q' smem row
#define VSTR 136                          // halfs per Vt smem row
#define KBYTES (128 * QSTR * 2)           // 51200
#define VBYTES (64 * VSTR * 2)            // 17408
#define ABUF   (KBYTES + 2 * VBYTES)      // 86016
#define ATTN_SMEM (2 * ABUF)              // 172032

__global__ __launch_bounds__(256)
void attn_mma_kernel(const __nv_bfloat16* __restrict__ Qa,
                     const __nv_bfloat16* __restrict__ Ka,
                     const __nv_bfloat16* __restrict__ Vh,
                     const __nv_bfloat16* __restrict__ Vl,
                     __nv_bfloat16* __restrict__ Ax)
{
    extern __shared__ char smem[];
    const uint32_t smb = smem_u32(smem);
    const int tid = threadIdx.x, lane = tid & 31, w = tid >> 5;
    const int bh = blockIdx.y;
    const int q0 = blockIdx.x * 128;
    const int wq = w * 16;

    const __nv_bfloat16* Qg  = Qa + ((size_t)bh * 2048 + q0) * 192;
    const __nv_bfloat16* Kg  = Ka + (size_t)bh * 2048 * 192;
    const __nv_bfloat16* Vhg = Vh + (size_t)bh * 64 * 2048;
    const __nv_bfloat16* Vlg = Vl + (size_t)bh * 64 * 2048;

    const uint32_t a_row = lane & 15, a_kof = ((lane >> 4) & 1) * 8;
    const uint32_t b_row = ((lane >> 4) & 1) * 8 + (lane & 7);
    const uint32_t b_kof = ((lane >> 3) & 1) * 8;
    const int r0 = lane >> 2, c0 = (lane & 3) * 2;

    auto load_tile = [&](int kt) {
        uint32_t bb = smb + (uint32_t)(kt & 1) * ABUF;
        int k0 = kt * 128;
#pragma unroll
        for (int j = 0; j < 12; j++) {          // K' tile: 128 x 192 halfs
            int c = tid + 256 * j;
            int row = c / 24, cc = c % 24;
            cp_async16(bb + row * (QSTR * 2) + cc * 16,
                       Kg + ((size_t)(k0 + row)) * 192 + cc * 8);
        }
#pragma unroll
        for (int j = 0; j < 4; j++) {           // Vt hi: 64 x 128 halfs
            int c = tid + 256 * j;
            int row = c >> 4, cc = c & 15;
            cp_async16(bb + KBYTES + row * (VSTR * 2) + cc * 16,
                       Vhg + (size_t)row * 2048 + k0 + cc * 8);
        }
#pragma unroll
        for (int j = 0; j < 4; j++) {           // Vt lo
            int c = tid + 256 * j;
            int row = c >> 4, cc = c & 15;
            cp_async16(bb + KBYTES + VBYTES + row * (VSTR * 2) + cc * 16,
                       Vlg + (size_t)row * 2048 + k0 + cc * 8);
        }
    };

    // prologue: Q' tile into buf1, tile0 into buf0
#pragma unroll
    for (int j = 0; j < 12; j++) {
        int c = tid + 256 * j;
        int row = c / 24, cc = c % 24;
        cp_async16(smb + ABUF + row * (QSTR * 2) + cc * 16,
                   Qg + (size_t)row * 192 + cc * 8);
    }
    asm volatile("cp.async.commit_group;" ::: "memory");
    load_tile(0);
    asm volatile("cp.async.commit_group;" ::: "memory");
    asm volatile("cp.async.wait_group 1;" ::: "memory");   // Q resident
    __syncthreads();

    uint32_t q[12][4];
#pragma unroll
    for (int ks = 0; ks < 12; ks++)
        ldsm_x4(q[ks], smb + ABUF + (wq + a_row) * (QSTR * 2) + (ks * 16 + a_kof) * 2);
    __syncthreads();                                       // buf1 free for tile1

    float o[8][4];
#pragma unroll
    for (int f = 0; f < 8; f++)
#pragma unroll
        for (int j = 0; j < 4; j++) o[f][j] = 0.f;
    float m2[2] = {-1e30f, -1e30f}, l2[2] = {0.f, 0.f};

    for (int kt = 0; kt < 16; kt++) {
        if (kt < 15) load_tile(kt + 1);
        asm volatile("cp.async.commit_group;" ::: "memory");
        if (kt < 15) asm volatile("cp.async.wait_group 1;" ::: "memory");
        else         asm volatile("cp.async.wait_group 0;" ::: "memory");
        __syncthreads();

        uint32_t kb = smb + (uint32_t)(kt & 1) * ABUF;

        // ---- S = Q' K'^T  (16 n8-frags, 12 k16 steps) ----
        float sacc[16][4];
#pragma unroll
        for (int f = 0; f < 16; f++)
#pragma unroll
            for (int j = 0; j < 4; j++) sacc[f][j] = 0.f;
#pragma unroll
        for (int ks = 0; ks < 12; ks++) {
#pragma unroll
            for (int nq = 0; nq < 8; nq++) {
                uint32_t bf[4];
                ldsm_x4(bf, kb + (nq * 16 + b_row) * (QSTR * 2) + (ks * 16 + b_kof) * 2);
                mma16816(sacc[2 * nq],     q[ks], bf[0], bf[1]);
                mma16816(sacc[2 * nq + 1], q[ks], bf[2], bf[3]);
            }
        }

        // ---- online softmax (base-2; Q pre-scaled by 0.125*log2e) ----
#pragma unroll
        for (int rh = 0; rh < 2; rh++) {
            float mt = -1e30f;
#pragma unroll
            for (int f = 0; f < 16; f++)
                mt = fmaxf(mt, fmaxf(sacc[f][2 * rh], sacc[f][2 * rh + 1]));
            mt = fmaxf(mt, __shfl_xor_sync(0xffffffffu, mt, 1));
            mt = fmaxf(mt, __shfl_xor_sync(0xffffffffu, mt, 2));
            float mn = fmaxf(m2[rh], mt);
            float sc = exp2f(m2[rh] - mn);
            m2[rh] = mn;
            float rs = 0.f;
#pragma unroll
            for (int f = 0; f < 16; f++) {
                float p0 = exp2f(sacc[f][2 * rh] - mn);
                float p1 = exp2f(sacc[f][2 * rh + 1] - mn);
                sacc[f][2 * rh] = p0; sacc[f][2 * rh + 1] = p1;
                rs += p0 + p1;
            }
            rs += __shfl_xor_sync(0xffffffffu, rs, 1);
            rs += __shfl_xor_sync(0xffffffffu, rs, 2);
            l2[rh] = l2[rh] * sc + rs;
#pragma unroll
            for (int f = 0; f < 8; f++) {
                o[f][2 * rh] *= sc; o[f][2 * rh + 1] *= sc;
            }
        }

        // ---- O += Ph Vh + Ph Vl + Pl Vh ----
        uint32_t vhb = kb + KBYTES, vlb = vhb + VBYTES;
#pragma unroll
        for (int kf = 0; kf < 8; kf++) {
            uint32_t ah[4], al[4];
#pragma unroll
            for (int jj = 0; jj < 2; jj++) {          // jj=0 -> frag 2kf (k0-7), jj=1 -> 2kf+1 (k8-15)
                float* p = sacc[2 * kf + jj];
                __nv_bfloat16 h0, l0, h1, l1, h2, l3h, h3, l3;
                bsplit(p[0], h0, l0); bsplit(p[1], h1, l1);
                ah[jj * 2]     = packh(h0, h1);
                al[jj * 2]     = packh(l0, l1);
                bsplit(p[2], h2, l3h); bsplit(p[3], h3, l3);
                ah[jj * 2 + 1] = packh(h2, h3);
                al[jj * 2 + 1] = packh(l3h, l3);
            }
#pragma unroll
            for (int ng = 0; ng < 4; ng++) {
                uint32_t bh4[4], bl4[4];
                ldsm_x4(bh4, vhb + (ng * 16 + b_row) * (VSTR * 2) + (kf * 16 + b_kof) * 2);
                ldsm_x4(bl4, vlb + (ng * 16 + b_row) * (VSTR * 2) + (kf * 16 + b_kof) * 2);
                mma16816(o[2 * ng],     ah, bh4[0], bh4[1]);
                mma16816(o[2 * ng + 1], ah, bh4[2], bh4[3]);
                mma16816(o[2 * ng],     ah, bl4[0], bl4[1]);
                mma16816(o[2 * ng + 1], ah, bl4[2], bl4[3]);
                mma16816(o[2 * ng],     al, bh4[0], bh4[1]);
                mma16816(o[2 * ng + 1], al, bh4[2], bh4[3]);
            }
        }
        __syncthreads();   // compute done before next-next buffer overwrite
    }

    // ---- epilogue: x = O/l, write [hi|hi|lo] rows of g_Ax ----
    const int b = bh >> 4, h = bh & 15;
    float inv0 = 1.f / l2[0], inv1 = 1.f / l2[1];
#pragma unroll
    for (int f = 0; f < 8; f++) {
        int col = h * 64 + f * 8 + c0;
#pragma unroll
        for (int rh = 0; rh < 2; rh++) {
            int gq = q0 + wq + r0 + rh * 8;
            size_t base = (size_t)(b * 2048 + gq) * 3072 + col;
            float inv = rh ? inv1 : inv0;
            float x0 = o[f][2 * rh] * inv, x1 = o[f][2 * rh + 1] * inv;
            __nv_bfloat16 h0, l0, h1, l1;
            bsplit(x0, h0, l0); bsplit(x1, h1, l1);
            uint32_t hp = packh(h0, h1), lp = packh(l0, l1);
            *reinterpret_cast<uint32_t*>(&Ax[base])        = hp;
            *reinterpret_cast<uint32_t*>(&Ax[base + 1024]) = hp;
            *reinterpret_cast<uint32_t*>(&Ax[base + 2048]) = lp;
        }
    }
}

// ---------------------------------------------------------------------------
extern "C" void kernel_launch(void* const* d_in, const int* in_sizes, int n_in,
                              void* d_out, int out_size)
{
    const float* xq  = (const float*)d_in[0];
    const float* xkv = (const float*)d_in[1];
    const float* Wq  = (const float*)d_in[2];
    const float* bq  = (const float*)d_in[3];
    const float* Wk  = (const float*)d_in[4];
    const float* bk  = (const float*)d_in[5];
    const float* Wv  = (const float*)d_in[6];
    const float* bv  = (const float*)d_in[7];
    const float* Wo  = (const float*)d_in[8];
    const float* bo  = (const float*)d_in[9];
    float* out = (float*)d_out;

    __nv_bfloat16 *aq, *akv, *ax, *bqW, *bkW, *bvW, *boW, *qa, *ka, *vth, *vtl;
    cudaGetSymbolAddress((void**)&aq,  g_Aq);
    cudaGetSymbolAddress((void**)&akv, g_Akv);
    cudaGetSymbolAddress((void**)&ax,  g_Ax);
    cudaGetSymbolAddress((void**)&bqW, g_Bq);
    cudaGetSymbolAddress((void**)&bkW, g_Bk);
    cudaGetSymbolAddress((void**)&bvW, g_Bv);
    cudaGetSymbolAddress((void**)&boW, g_Bo);
    cudaGetSymbolAddress((void**)&qa,  g_Qa);
    cudaGetSymbolAddress((void**)&ka,  g_Ka);
    cudaGetSymbolAddress((void**)&vth, g_Vth);
    cudaGetSymbolAddress((void**)&vtl, g_Vtl);

    // input splits
    {
        int nb = (TOK * Dd / 4 + 255) / 256;
        split_act_kernel<<<nb, 256>>>(xq,  aq,  TOK, Dd);
        split_act_kernel<<<nb, 256>>>(xkv, akv, TOK, Dd);
    }
    {
        dim3 gw(NHD / 32, Dd / 32), bw(32, 32);
        split_wt_kernel<<<gw, bw>>>(Wq, bqW, Dd, NHD);
        split_wt_kernel<<<gw, bw>>>(Wk, bkW, Dd, NHD);
        split_wt_kernel<<<gw, bw>>>(Wv, bvW, Dd, NHD);
        split_wt_kernel<<<dim3(Dd / 32, NHD / 32), bw>>>(Wo, boW, NHD, Dd);
    }

    static const int GEMM_SMEM = NSTAGE * STAGE_BYTES;   // 61440
    cudaFuncSetAttribute(gemm_mma_kernel<0>, cudaFuncAttributeMaxDynamicSharedMemorySize, GEMM_SMEM);
    cudaFuncSetAttribute(gemm_mma_kernel<1>, cudaFuncAttributeMaxDynamicSharedMemorySize, GEMM_SMEM);
    cudaFuncSetAttribute(gemm_mma_kernel<2>, cudaFuncAttributeMaxDynamicSharedMemorySize, GEMM_SMEM);
    cudaFuncSetAttribute(gemm_mma_kernel<3>, cudaFuncAttributeMaxDynamicSharedMemorySize, GEMM_SMEM);
    cudaFuncSetAttribute(attn_mma_kernel,    cudaFuncAttributeMaxDynamicSharedMemorySize, ATTN_SMEM);

    dim3 gg(NHD / 128, TOK / 128);                       // (8, 64)
    const float ALPHA_Q = 0.125f * 1.4426950408889634f;  // 1/sqrt(64) * log2(e)

    // projections -> attention layouts
    gemm_mma_kernel<1><<<gg, 256, GEMM_SMEM>>>(aq,  bqW, bq, nullptr, qa,  nullptr, NHD, ALPHA_Q);
    gemm_mma_kernel<2><<<gg, 256, GEMM_SMEM>>>(akv, bkW, bk, nullptr, ka,  nullptr, NHD, 1.0f);
    gemm_mma_kernel<3><<<gg, 256, GEMM_SMEM>>>(akv, bvW, bv, nullptr, vth, vtl,     NHD, 1.0f);

    // attention (tensor-core) -> g_Ax (pre-split for out projection)
    dim3 ga(Ss / 128, BH);                               // (16, 64)
    attn_mma_kernel<<<ga, 256, ATTN_SMEM>>>(qa, ka, vth, vtl, ax);

    // output projection
    gemm_mma_kernel<0><<<gg, 256, GEMM_SMEM>>>(ax, boW, bo, out, nullptr, nullptr, Dd, 1.0f);
}